// round 3
// baseline (speedup 1.0000x reference)
#include <cuda_runtime.h>
#include <cstdint>

// VectorQuantizer — bit-replication of the JAX reference numerics.
//   dist_k = fl( fl(||z||^2 + ||e_k||^2) - 2 * C_k ),  C_k = ascending-d FFMA dot from 0
//   argmin, first-index tie-break; Zq_out = fl(z + fl(e - z)); loss = 1.25*mean((e-z)^2)

typedef unsigned long long u64;

#define DDIM 64
#define KC 512
#define KHALF 256
#define HW 4096
#define CHW 262144
#define NVEC 131072
#define THREADS 256
#define NBLOCKS 256          // NVEC / (THREADS * 2 vectors/thread)
#define ZQ_ELEMS 8388608
#define KSTRIDE 258          // u64 row stride (16B-aligned pairs, staging-bank relief)
#define TK 8                 // codes per register tile

__device__ float g_blocksums[NBLOCKS];
__device__ unsigned int g_done = 0;

__device__ __forceinline__ u64 fma2(u64 a, u64 b, u64 c) {
    u64 d; asm("fma.rn.f32x2 %0,%1,%2,%3;" : "=l"(d) : "l"(a), "l"(b), "l"(c)); return d;
}
__device__ __forceinline__ u64 pack2(float lo, float hi) {
    u64 d; asm("mov.b64 %0,{%1,%2};" : "=l"(d) : "f"(lo), "f"(hi)); return d;
}
__device__ __forceinline__ void unpack2(u64 a, float& lo, float& hi) {
    asm("mov.b64 {%0,%1},%2;" : "=f"(lo), "=f"(hi) : "l"(a));
}
__device__ __forceinline__ void lds_v2u64(u64& a, u64& b, uint32_t addr) {
    asm volatile("ld.shared.v2.u64 {%0,%1},[%2];" : "=l"(a), "=l"(b) : "r"(addr));
}
__device__ __forceinline__ void lds_row(u64* buf, uint32_t addr) {
    lds_v2u64(buf[0], buf[1], addr);
    lds_v2u64(buf[2], buf[3], addr + 16);
    lds_v2u64(buf[4], buf[5], addr + 32);
    lds_v2u64(buf[6], buf[7], addr + 48);
}

__global__ void __launch_bounds__(THREADS, 1)
vq_main_kernel(const float* __restrict__ inp, const float* __restrict__ E,
               float* __restrict__ out, int zq_off)
{
    extern __shared__ u64 sm[];                 // Edup: [64][KSTRIDE] u64, (e,e) pairs
    float* Bsh = (float*)(sm + DDIM * KSTRIDE); // ||e_k||^2, 512 floats
    __shared__ float red[8];
    __shared__ unsigned int s_rank;

    const int tid = threadIdx.x;
    uint32_t sE = (uint32_t)__cvta_generic_to_shared(sm);

    // --- B_k = sum_d fl(e^2), ascending d ---
    for (int k = tid; k < KC; k += THREADS) {
        const float* er = E + k * DDIM;
        float bsum = 0.f;
        #pragma unroll
        for (int d = 0; d < DDIM; d++) { float e = er[d]; bsum = bsum + e * e; }
        Bsh[k] = bsum;
    }

    // --- load 2 vectors per thread (lane-lo = n0, lane-hi = n1) ---
    const int n0 = blockIdx.x * THREADS + tid;
    const int n1 = n0 + (NVEC / 2);
    const int b0 = n0 >> 12, hw0 = n0 & 4095;
    const int b1 = n1 >> 12, hw1 = n1 & 4095;
    const float* z0p = inp + (size_t)b0 * CHW + hw0;
    const float* z1p = inp + (size_t)b1 * CHW + hw1;

    u64 zp[DDIM];
    float A0 = 0.f, A1 = 0.f;
    #pragma unroll
    for (int d = 0; d < DDIM; d++) {
        float a = __ldg(z0p + (size_t)d * HW);
        float c = __ldg(z1p + (size_t)d * HW);
        A0 = A0 + a * a; A1 = A1 + c * c;
        zp[d] = pack2(a, c);
    }

    float best0 = 3.402823466e38f, best1 = 3.402823466e38f;
    int bi0 = 0, bi1 = 0;

    for (int pass = 0; pass < 2; pass++) {
        const int k0 = pass * KHALF;
        __syncthreads();   // previous-pass readers done before restaging
        for (int idx = tid; idx < KHALF * DDIM; idx += THREADS) {
            int k = idx >> 6, d = idx & 63;
            float e = __ldg(E + (k0 + k) * DDIM + d);
            sm[(size_t)d * KSTRIDE + k] = pack2(e, e);
        }
        __syncthreads();

        for (int tile = 0; tile < KHALF; tile += TK) {
            uint32_t base = sE + (uint32_t)tile * 8;
            u64 bufA[TK], bufB[TK];
            lds_row(bufA, base);                       // row d=0
            u64 acc[TK];
            #pragma unroll
            for (int c = 0; c < TK; c++) acc[c] = 0ull;

            #pragma unroll
            for (int d = 0; d < DDIM; d += 2) {
                if (d + 1 < DDIM) lds_row(bufB, base + (uint32_t)(d + 1) * (KSTRIDE * 8));
                #pragma unroll
                for (int c = 0; c < TK; c++) acc[c] = fma2(zp[d], bufA[c], acc[c]);
                if (d + 2 < DDIM) lds_row(bufA, base + (uint32_t)(d + 2) * (KSTRIDE * 8));
                #pragma unroll
                for (int c = 0; c < TK; c++) acc[c] = fma2(zp[d + 1], bufB[c], acc[c]);
            }

            // finalize ascending code order (first-index tie-break via strict <)
            #pragma unroll
            for (int c = 0; c < TK; c++) {
                const int k = k0 + tile + c;
                float C0, C1; unpack2(acc[c], C0, C1);
                const float Bk = Bsh[k];
                float S0 = fmaf(-2.f, C0, A0 + Bk);
                if (S0 < best0) { best0 = S0; bi0 = k; }
                float S1 = fmaf(-2.f, C1, A1 + Bk);
                if (S1 < best1) { best1 = S1; bi1 = k; }
            }
        }
    }

    // --- emit Zq = fl(z + fl(e - z)) + loss partial ---
    float ls = 0.f;
    {
        const float* er0 = E + bi0 * DDIM;
        const float* er1 = E + bi1 * DDIM;
        float* o0 = out + zq_off + (size_t)b0 * CHW + hw0;
        float* o1 = out + zq_off + (size_t)b1 * CHW + hw1;
        #pragma unroll
        for (int d = 0; d < DDIM; d++) {
            float zlo, zhi; unpack2(zp[d], zlo, zhi);
            float t0 = __ldg(er0 + d) - zlo;
            float t1 = __ldg(er1 + d) - zhi;
            ls += t0 * t0;
            ls += t1 * t1;
            o0[(size_t)d * HW] = zlo + t0;
            o1[(size_t)d * HW] = zhi + t1;
        }
    }

    // --- deterministic block reduction + fused last-block loss finalize ---
    #pragma unroll
    for (int off = 16; off; off >>= 1) ls += __shfl_down_sync(0xffffffffu, ls, off);
    int wid = tid >> 5, lane = tid & 31;
    if (lane == 0) red[wid] = ls;
    __syncthreads();
    if (tid == 0) {
        float t = 0.f;
        #pragma unroll
        for (int i = 0; i < 8; i++) t += red[i];
        g_blocksums[blockIdx.x] = t;
        __threadfence();
        s_rank = atomicAdd(&g_done, 1u);
    }
    __syncthreads();
    if (s_rank == NBLOCKS - 1) {           // last block finishes the loss
        if (tid < 32) {
            double s = 0.0;
            for (int i = tid; i < NBLOCKS; i += 32) s += (double)g_blocksums[i];
            #pragma unroll
            for (int off = 16; off; off >>= 1) s += __shfl_down_sync(0xffffffffu, s, off);
            if (tid == 0) {
                if (zq_off >= 1) out[0] = (float)(s * (1.25 / 8388608.0));
                g_done = 0;                // reset for next graph replay
            }
        }
    }
}

extern "C" void kernel_launch(void* const* d_in, const int* in_sizes, int n_in,
                              void* d_out, int out_size)
{
    const float* inp = (const float*)d_in[0];  // [32,64,64,64] fp32
    const float* E   = (const float*)d_in[1];  // [512,64] fp32
    float* out = (float*)d_out;

    int zq_off = (out_size > ZQ_ELEMS) ? (out_size - ZQ_ELEMS) : 0;

    const int smem_bytes = DDIM * KSTRIDE * 8 + KC * 4;  // 134144
    cudaFuncSetAttribute(vq_main_kernel, cudaFuncAttributeMaxDynamicSharedMemorySize, smem_bytes);

    vq_main_kernel<<<NBLOCKS, THREADS, smem_bytes>>>(inp, E, out, zq_off);
}

// round 4
// speedup vs baseline: 1.9755x; 1.9755x over previous
#include <cuda_runtime.h>
#include <cstdint>

// VectorQuantizer — bit-replication of the JAX reference numerics.
//   dist_k = fl( fl(||z||^2 + ||e_k||^2) - 2 * C_k ),  C_k = ascending-d FFMA dot from 0
//   argmin, first-index tie-break; Zq_out = fl(z + fl(e - z)); loss = 1.25*mean((e-z)^2)
//
// Lane mapping (round 4): f32x2 lanes carry TWO ADJACENT CODES (e_k, e_k+1), loaded as
// natural u64 pairs from a [d][k]-transposed smem tile (NO duplication -> 1 LDS : 4 FFMA2).
// z is duplicated (z,z) per d via register MOVs (cheap, alu pipe).

typedef unsigned long long u64;

#define DDIM 64
#define KC 512
#define KHALF 256          // codes staged per pass (2 passes, 64KB smem each)
#define HW 4096
#define CHW 262144
#define NVEC 131072
#define THREADS 256
#define NBLOCKS 256        // NVEC / (THREADS * 2 vectors/thread)
#define ZQ_ELEMS 8388608
#define CT 16              // codes per register tile (8 u64 lanes-pairs)

__device__ float g_blocksums[NBLOCKS];
__device__ unsigned int g_done = 0;

__device__ __forceinline__ u64 fma2(u64 a, u64 b, u64 c) {
    u64 d; asm("fma.rn.f32x2 %0,%1,%2,%3;" : "=l"(d) : "l"(a), "l"(b), "l"(c)); return d;
}
__device__ __forceinline__ u64 pack2(float lo, float hi) {
    u64 d; asm("mov.b64 %0,{%1,%2};" : "=l"(d) : "f"(lo), "f"(hi)); return d;
}
__device__ __forceinline__ void unpack2(u64 a, float& lo, float& hi) {
    asm("mov.b64 {%0,%1},%2;" : "=f"(lo), "=f"(hi) : "l"(a));
}
__device__ __forceinline__ void lds_v2u64(u64& a, u64& b, uint32_t addr) {
    asm volatile("ld.shared.v2.u64 {%0,%1},[%2];" : "=l"(a), "=l"(b) : "r"(addr));
}
// load 16 consecutive floats (= 8 natural (e_k,e_k+1) u64 pairs)
__device__ __forceinline__ void lds_row16(u64* buf, uint32_t addr) {
    lds_v2u64(buf[0], buf[1], addr);
    lds_v2u64(buf[2], buf[3], addr + 16);
    lds_v2u64(buf[4], buf[5], addr + 32);
    lds_v2u64(buf[6], buf[7], addr + 48);
}

__global__ void __launch_bounds__(THREADS, 1)
vq_main_kernel(const float* __restrict__ inp, const float* __restrict__ E,
               float* __restrict__ out, int zq_off)
{
    extern __shared__ float sm[];            // Esh: [DDIM][KHALF] f32 (transposed tile)
    float* Bsh = sm + DDIM * KHALF;          // ||e_k||^2, 512 floats
    __shared__ float red[8];
    __shared__ unsigned int s_rank;

    const int tid = threadIdx.x;
    uint32_t sE = (uint32_t)__cvta_generic_to_shared(sm);

    // --- B_k = sum_d fl(e^2), ascending d ---
    for (int k = tid; k < KC; k += THREADS) {
        const float* er = E + k * DDIM;
        float bsum = 0.f;
        #pragma unroll
        for (int d = 0; d < DDIM; d++) { float e = er[d]; bsum = bsum + e * e; }
        Bsh[k] = bsum;
    }

    // --- load this thread's 2 vectors into registers ---
    const int n0 = blockIdx.x * THREADS + tid;
    const int n1 = n0 + (NVEC / 2);
    const int b0 = n0 >> 12, hw0 = n0 & 4095;
    const int b1 = n1 >> 12, hw1 = n1 & 4095;
    const float* z0p = inp + (size_t)b0 * CHW + hw0;
    const float* z1p = inp + (size_t)b1 * CHW + hw1;

    float zA[DDIM], zB[DDIM];
    float A0 = 0.f, A1 = 0.f;                // ||z||^2 (order shift commutes; any order OK)
    #pragma unroll
    for (int d = 0; d < DDIM; d++) {
        float a = __ldg(z0p + (size_t)d * HW);
        float c = __ldg(z1p + (size_t)d * HW);
        A0 = A0 + a * a; A1 = A1 + c * c;
        zA[d] = a; zB[d] = c;
    }

    float best0 = 3.402823466e38f, best1 = 3.402823466e38f;
    int bi0 = 0, bi1 = 0;

    for (int pass = 0; pass < 2; pass++) {
        const int k0 = pass * KHALF;
        __syncthreads();   // previous-pass readers done before restaging
        // stage E transposed: Esh[d][k] = E[k0+k][d]; stores conflict-free (k fast)
        for (int idx = tid; idx < KHALF * DDIM; idx += THREADS) {
            int d = idx >> 8, k = idx & 255;
            sm[d * KHALF + k] = __ldg(E + (size_t)(k0 + k) * DDIM + d);
        }
        __syncthreads();

        for (int kt = 0; kt < KHALF; kt += CT) {
            uint32_t base = sE + (uint32_t)kt * 4;
            u64 ep[2][CT / 2];
            lds_row16(ep[0], base);                    // row d=0
            u64 acc0[CT / 2], acc1[CT / 2];
            #pragma unroll
            for (int c = 0; c < CT / 2; c++) { acc0[c] = 0ull; acc1[c] = 0ull; }

            #pragma unroll
            for (int d = 0; d < DDIM; d++) {
                if (d + 1 < DDIM)
                    lds_row16(ep[(d + 1) & 1], base + (uint32_t)(d + 1) * (KHALF * 4));
                const u64 za = pack2(zA[d], zA[d]);    // register duplicate, no load
                const u64 zb = pack2(zB[d], zB[d]);
                const u64* e = ep[d & 1];
                #pragma unroll
                for (int c = 0; c < CT / 2; c++) acc0[c] = fma2(za, e[c], acc0[c]);
                #pragma unroll
                for (int c = 0; c < CT / 2; c++) acc1[c] = fma2(zb, e[c], acc1[c]);
            }

            // finalize, ascending code order (first-index tie-break via strict <)
            #pragma unroll
            for (int c = 0; c < CT / 2; c++) {
                const int k = k0 + kt + 2 * c;
                float Clo, Chi;
                const float Bk = Bsh[k], Bk1 = Bsh[k + 1];
                unpack2(acc0[c], Clo, Chi);
                float S;
                S = fmaf(-2.f, Clo, A0 + Bk);  if (S < best0) { best0 = S; bi0 = k; }
                S = fmaf(-2.f, Chi, A0 + Bk1); if (S < best0) { best0 = S; bi0 = k + 1; }
                unpack2(acc1[c], Clo, Chi);
                S = fmaf(-2.f, Clo, A1 + Bk);  if (S < best1) { best1 = S; bi1 = k; }
                S = fmaf(-2.f, Chi, A1 + Bk1); if (S < best1) { best1 = S; bi1 = k + 1; }
            }
        }
    }

    // --- emit Zq = fl(z + fl(e - z)) + loss partial ---
    float ls = 0.f;
    {
        const float* er0 = E + (size_t)bi0 * DDIM;
        const float* er1 = E + (size_t)bi1 * DDIM;
        float* o0 = out + zq_off + (size_t)b0 * CHW + hw0;
        float* o1 = out + zq_off + (size_t)b1 * CHW + hw1;
        #pragma unroll
        for (int d = 0; d < DDIM; d++) {
            float t0 = __ldg(er0 + d) - zA[d];
            float t1 = __ldg(er1 + d) - zB[d];
            ls += t0 * t0;
            ls += t1 * t1;
            o0[(size_t)d * HW] = zA[d] + t0;
            o1[(size_t)d * HW] = zB[d] + t1;
        }
    }

    // --- deterministic block reduction + fused last-block loss finalize ---
    #pragma unroll
    for (int off = 16; off; off >>= 1) ls += __shfl_down_sync(0xffffffffu, ls, off);
    int wid = tid >> 5, lane = tid & 31;
    if (lane == 0) red[wid] = ls;
    __syncthreads();
    if (tid == 0) {
        float t = 0.f;
        #pragma unroll
        for (int i = 0; i < 8; i++) t += red[i];
        g_blocksums[blockIdx.x] = t;
        __threadfence();
        s_rank = atomicAdd(&g_done, 1u);
    }
    __syncthreads();
    if (s_rank == NBLOCKS - 1) {
        if (tid < 32) {
            double s = 0.0;
            for (int i = tid; i < NBLOCKS; i += 32) s += (double)g_blocksums[i];
            #pragma unroll
            for (int off = 16; off; off >>= 1) s += __shfl_down_sync(0xffffffffu, s, off);
            if (tid == 0) {
                if (zq_off >= 1) out[0] = (float)(s * (1.25 / 8388608.0));
                g_done = 0;    // reset for next graph replay
            }
        }
    }
}

extern "C" void kernel_launch(void* const* d_in, const int* in_sizes, int n_in,
                              void* d_out, int out_size)
{
    const float* inp = (const float*)d_in[0];  // [32,64,64,64] fp32
    const float* E   = (const float*)d_in[1];  // [512,64] fp32
    float* out = (float*)d_out;

    int zq_off = (out_size > ZQ_ELEMS) ? (out_size - ZQ_ELEMS) : 0;

    const int smem_bytes = (DDIM * KHALF + KC) * 4;  // 65536 + 2048 = 67584
    cudaFuncSetAttribute(vq_main_kernel, cudaFuncAttributeMaxDynamicSharedMemorySize, smem_bytes);

    vq_main_kernel<<<NBLOCKS, THREADS, smem_bytes>>>(inp, E, out, zq_off);
}